// round 14
// baseline (speedup 1.0000x reference)
#include <cuda_runtime.h>
#include <stdint.h>

// Problem constants (fixed by the reference)
#define N_POI    10000
#define V_VOCAB  20000
#define BS       6400          // B*S = 64*100
#define N_VEC    (N_POI / 4)   // 2500 float4 per row
#define BIG_INV  (1.0f / 9999999.99f)

__device__ __forceinline__ float4 recip_mask(float4 v) {
    float4 o;
    o.x = (v.x == 0.0f) ? BIG_INV : __fdividef(1.0f, v.x);
    o.y = (v.y == 0.0f) ? BIG_INV : __fdividef(1.0f, v.y);
    o.z = (v.z == 0.0f) ? BIG_INV : __fdividef(1.0f, v.z);
    o.w = (v.w == 0.0f) ? BIG_INV : __fdividef(1.0f, v.w);
    return o;
}

// ---------------------------------------------------------------------------
// Burst-phased whole-row kernel: one block per output row, 256 threads.
// Mechanism under test: longer same-direction DRAM bursts. Phase 1 issues
// EIGHT independent float4 loads per thread (a 32KB read burst per block),
// then eight stores (32KB write burst); phase 2 handles the 452-float4
// remainder with 2 predicated load/store pairs. Fewer read<->write
// direction switches at the memory controller should lift achievable HBM
// bandwidth above the ~74% plateau seen with 4-5-deep batching.
//
// Reads use default policy (L2 dedups duplicate gathered rows -- measured
// at the unique-row floor); writes use __stcs (output never re-read).
//
// Index resolution: two warp-uniform loads (inputs_poi -> venueid2coor),
// broadcast-coalesced, L2-hot after the first wave. No barrier, no smem.
// Index dtype auto-detected: int64 LE values in [0,10000) have zero upper
// 32-bit words; 16 consecutive zero upper-words on int32 data ~ prob 1e-64.
// ---------------------------------------------------------------------------
__global__ void __launch_bounds__(256)
fused_gather_recip(const void* __restrict__ v2c,
                   const void* __restrict__ poi,
                   const float* __restrict__ mat,
                   float* __restrict__ out) {
    const int orow = blockIdx.x;

    // dtype detection (L1-broadcast loads, warp-uniform)
    bool is64 = true;
    {
        const unsigned long long* p = (const unsigned long long*)v2c;
        #pragma unroll
        for (int i = 0; i < 16; i++)
            if ((p[i] >> 32) != 0ull) { is64 = false; break; }
    }

    // resolve venueid2coor[inputs_poi[orow]] (warp-uniform, L2-hot)
    int srow;
    if (is64) {
        long long vid = ((const long long*)poi)[orow];
        srow = (int)((const long long*)v2c)[vid];
    } else {
        int vid = ((const int*)poi)[orow];
        srow = ((const int*)v2c)[vid];
    }

    const float4* __restrict__ src =
        (const float4*)(mat + (long long)srow * N_POI);
    float4* __restrict__ dst =
        (float4*)(out + (long long)orow * N_POI);

    const int c = threadIdx.x;

    // ---- Phase 1: 8-deep read burst, then 8-deep write burst (2048 f4) ----
    float4 v[8];
    #pragma unroll
    for (int i = 0; i < 8; i++)
        v[i] = src[c + i * 256];
    #pragma unroll
    for (int i = 0; i < 8; i++)
        __stcs(&dst[c + i * 256], recip_mask(v[i]));

    // ---- Phase 2: remainder 452 f4 (2048..2499), 2 predicated pairs ------
    {
        const int  c0 = 2048 + c;             // 2048..2303, always valid
        const int  c1 = c0 + 256;             // 2304..2559, valid if < 2500
        const bool p1 = (c1 < N_VEC);
        float4 r0 = src[c0];
        float4 r1;
        if (p1) r1 = src[c1];
        __stcs(&dst[c0], recip_mask(r0));
        if (p1) __stcs(&dst[c1], recip_mask(r1));
    }
}

// ---------------------------------------------------------------------------
// Input order (setup_inputs dict order):
//   d_in[0] = venueid2coor        [V_VOCAB]       int64/int32 (detected)
//   d_in[1] = inputs_poi          [B*S]           int64/int32 (same dtype)
//   d_in[2] = poi_distance_matrix [N_POI*N_POI]   float32
// out: [B, S, N_POI] float32
// ---------------------------------------------------------------------------
extern "C" void kernel_launch(void* const* d_in, const int* in_sizes, int n_in,
                              void* d_out, int out_size) {
    const void*  v2c = d_in[0];
    const void*  poi = d_in[1];
    const float* mat = (const float*)d_in[2];
    float*       out = (float*)d_out;

    fused_gather_recip<<<BS, 256>>>(v2c, poi, mat, out);
}

// round 15
// speedup vs baseline: 1.0067x; 1.0067x over previous
#include <cuda_runtime.h>
#include <stdint.h>

// Problem constants (fixed by the reference)
#define N_POI    10000
#define V_VOCAB  20000
#define BS       6400          // B*S = 64*100
#define N_VEC    (N_POI / 4)   // 2500 float4 per row
#define BIG_INV  (1.0f / 9999999.99f)

__device__ __forceinline__ float4 recip_mask(float4 v) {
    float4 o;
    o.x = (v.x == 0.0f) ? BIG_INV : __fdividef(1.0f, v.x);
    o.y = (v.y == 0.0f) ? BIG_INV : __fdividef(1.0f, v.y);
    o.z = (v.z == 0.0f) ? BIG_INV : __fdividef(1.0f, v.z);
    o.w = (v.w == 0.0f) ? BIG_INV : __fdividef(1.0f, v.w);
    return o;
}

// ---------------------------------------------------------------------------
// Maximal-burst whole-row kernel: one block per output row, 256 threads.
// The ENTIRE 40KB row is read in one burst (9 unconditional + 1 predicated
// float4 loads per thread, all issued before any store), then the entire
// row is written in one burst. Zero read->write direction changes within a
// block's lifetime -- the limit case of the turnaround-amortization
// mechanism that gave +1.5% BW at 8-deep bursts. Occupancy drops to
// ~4-5 CTA/SM from register pressure, which is still ~10x the in-flight
// bytes needed to sustain peak BW (not binding).
//
// Reads use default policy (L2 dedups duplicate gathered rows -- measured
// at the unique-row floor); writes use __stcs (output never re-read).
//
// Index resolution: two warp-uniform loads (inputs_poi -> venueid2coor),
// broadcast-coalesced, L2-hot after the first wave. No barrier, no smem.
// Index dtype auto-detected: int64 LE values in [0,10000) have zero upper
// 32-bit words; 16 consecutive zero upper-words on int32 data ~ prob 1e-64.
// ---------------------------------------------------------------------------
__global__ void __launch_bounds__(256)
fused_gather_recip(const void* __restrict__ v2c,
                   const void* __restrict__ poi,
                   const float* __restrict__ mat,
                   float* __restrict__ out) {
    const int orow = blockIdx.x;

    // dtype detection (L1-broadcast loads, warp-uniform)
    bool is64 = true;
    {
        const unsigned long long* p = (const unsigned long long*)v2c;
        #pragma unroll
        for (int i = 0; i < 16; i++)
            if ((p[i] >> 32) != 0ull) { is64 = false; break; }
    }

    // resolve venueid2coor[inputs_poi[orow]] (warp-uniform, L2-hot)
    int srow;
    if (is64) {
        long long vid = ((const long long*)poi)[orow];
        srow = (int)((const long long*)v2c)[vid];
    } else {
        int vid = ((const int*)poi)[orow];
        srow = ((const int*)v2c)[vid];
    }

    const float4* __restrict__ src =
        (const float4*)(mat + (long long)srow * N_POI);
    float4* __restrict__ dst =
        (float4*)(out + (long long)orow * N_POI);

    const int  c  = threadIdx.x;
    // 2500 = 9*256 + 196: lanes c < 196 carry a 10th element.
    const bool pr = (c < N_VEC - 9 * 256);

    // ---- Single read burst: all loads issued before any store ----
    float4 v[9], vr;
    #pragma unroll
    for (int i = 0; i < 9; i++)
        v[i] = src[c + i * 256];
    if (pr) vr = src[c + 9 * 256];

    // ---- Single write burst ----
    #pragma unroll
    for (int i = 0; i < 9; i++)
        __stcs(&dst[c + i * 256], recip_mask(v[i]));
    if (pr) __stcs(&dst[c + 9 * 256], recip_mask(vr));
}

// ---------------------------------------------------------------------------
// Input order (setup_inputs dict order):
//   d_in[0] = venueid2coor        [V_VOCAB]       int64/int32 (detected)
//   d_in[1] = inputs_poi          [B*S]           int64/int32 (same dtype)
//   d_in[2] = poi_distance_matrix [N_POI*N_POI]   float32
// out: [B, S, N_POI] float32
// ---------------------------------------------------------------------------
extern "C" void kernel_launch(void* const* d_in, const int* in_sizes, int n_in,
                              void* d_out, int out_size) {
    const void*  v2c = d_in[0];
    const void*  poi = d_in[1];
    const float* mat = (const float*)d_in[2];
    float*       out = (float*)d_out;

    fused_gather_recip<<<BS, 256>>>(v2c, poi, mat, out);
}